// round 1
// baseline (speedup 1.0000x reference)
#include <cuda_runtime.h>
#include <math.h>

#define Dd 768
#define Hh 768
#define Ee 128
#define Bb 32
#define Ss 128
#define LN_EPS 1e-5f

// Scratch (static device allocations are allowed)
__device__ float g_q[Ee * Ss * Hh];   // [E*S, H]  ~50.3 MB
__device__ float g_k[Bb * Ss * Hh];   // [B*S, H]  ~12.6 MB
__device__ float g_v[Bb * Ss * Hh];   // [B*S, H]  ~12.6 MB
__device__ float g_c[Ee * Hh];        // [E, H]

// ---------------------------------------------------------------------------
// Generic projection GEMM: Y[M,768] = X[M,768] @ W[768,768] + bias
// 128x128 CTA tile, BK=16, 256 threads, 8x8 per-thread microtile.
// ---------------------------------------------------------------------------
__global__ __launch_bounds__(256)
void proj_kernel(const float* __restrict__ X, const float* __restrict__ W,
                 const float* __restrict__ bias, float* __restrict__ Y)
{
    __shared__ float As[16][132];   // As[k][m] (transposed)
    __shared__ float Bs[16][132];   // Bs[k][n]

    const int tid = threadIdx.x;
    const int tx = tid & 15;
    const int ty = tid >> 4;
    const int m0 = blockIdx.y << 7;
    const int n0 = blockIdx.x << 7;
    const int ak = tid & 15;        // k index for A loads
    const int am = tid >> 4;        // base m index for A loads

    float c[8][8];
#pragma unroll
    for (int i = 0; i < 8; i++)
#pragma unroll
        for (int j = 0; j < 8; j++) c[i][j] = 0.0f;

    for (int kt = 0; kt < Dd / 16; ++kt) {
        __syncthreads();
        // A tile: X[m0+am+16i][kt*16+ak] -> As[ak][am+16i]
#pragma unroll
        for (int i = 0; i < 8; i++)
            As[ak][am + 16 * i] = X[(size_t)(m0 + am + 16 * i) * Dd + kt * 16 + ak];
        // B tile: W[kt*16+r][n0+c4..] -> Bs[r][c4..]
#pragma unroll
        for (int i = 0; i < 2; i++) {
            int id = tid + 256 * i;
            int r  = id >> 5;
            int c4 = (id & 31) * 4;
            *(float4*)&Bs[r][c4] =
                *(const float4*)&W[(size_t)(kt * 16 + r) * Hh + n0 + c4];
        }
        __syncthreads();

#pragma unroll
        for (int k = 0; k < 16; k++) {
            float a[8], bb[8];
            *(float4*)&a[0]  = *(const float4*)&As[k][ty * 8];
            *(float4*)&a[4]  = *(const float4*)&As[k][ty * 8 + 4];
            *(float4*)&bb[0] = *(const float4*)&Bs[k][tx * 8];
            *(float4*)&bb[4] = *(const float4*)&Bs[k][tx * 8 + 4];
#pragma unroll
            for (int i = 0; i < 8; i++)
#pragma unroll
                for (int j = 0; j < 8; j++)
                    c[i][j] += a[i] * bb[j];
        }
    }

#pragma unroll
    for (int i = 0; i < 8; i++) {
        int m = m0 + ty * 8 + i;
#pragma unroll
        for (int j = 0; j < 8; j++) {
            int n = n0 + tx * 8 + j;
            Y[(size_t)m * Hh + n] = c[i][j] + bias[n];
        }
    }
}

// ---------------------------------------------------------------------------
// Block reduction helper (256 threads)
// ---------------------------------------------------------------------------
__device__ __forceinline__ float block_reduce_sum(float v, float* red)
{
    const int tid = threadIdx.x;
#pragma unroll
    for (int o = 16; o > 0; o >>= 1) v += __shfl_xor_sync(0xffffffffu, v, o);
    if ((tid & 31) == 0) red[tid >> 5] = v;
    __syncthreads();
    if (tid < 8) {
        v = red[tid];
#pragma unroll
        for (int o = 4; o > 0; o >>= 1) v += __shfl_xor_sync(0x000000ffu, v, o);
        if (tid == 0) red[0] = v;
    }
    __syncthreads();
    v = red[0];
    __syncthreads();
    return v;
}

// ---------------------------------------------------------------------------
// Fused attention + mean + LN + dual-score kernel.
// One CTA per (e, b) pair: grid = E*B = 4096.
//   L = (Q_e @ K_b^T) * scale        [128 x 128]
//   P = softmax_t(L)  (in registers, row reductions via shfl over 16 lanes)
//   pbar[t] = sum_s P[s,t]           (smem atomics)
//   ctx[h]  = (1/S) * sum_t pbar[t] * V_b[t,h]
//   ctx_ln  = LN(ctx) * g + b
//   out[b,e] = 0.5 * (cls_fc[e]·ctx_ln + mcls[b]·ecls[e])
// ---------------------------------------------------------------------------
__global__ __launch_bounds__(256)
void attn_kernel(const float* __restrict__ ecls, const float* __restrict__ mcls,
                 const float* __restrict__ lng, const float* __restrict__ lnb,
                 float* __restrict__ out)
{
    __shared__ float As[16][132];   // Q: As[k][s]
    __shared__ float Bs[16][132];   // K: Bs[k][t]
    __shared__ float pbar[128];
    __shared__ float red[8];

    const int tid = threadIdx.x;
    const int tx = tid & 15;
    const int ty = tid >> 4;
    const int e = blockIdx.x >> 5;    // / B
    const int b = blockIdx.x & 31;    // % B

    const float* __restrict__ Q = g_q + (size_t)e * Ss * Hh;
    const float* __restrict__ K = g_k + (size_t)b * Ss * Hh;
    const float* __restrict__ V = g_v + (size_t)b * Ss * Hh;

    if (tid < 128) pbar[tid] = 0.0f;

    float c[8][8];
#pragma unroll
    for (int i = 0; i < 8; i++)
#pragma unroll
        for (int j = 0; j < 8; j++) c[i][j] = 0.0f;

    const int ak = tid & 15;
    const int am = tid >> 4;

    for (int kt = 0; kt < Hh / 16; ++kt) {
        __syncthreads();
#pragma unroll
        for (int i = 0; i < 8; i++) {
            As[ak][am + 16 * i] = Q[(size_t)(am + 16 * i) * Hh + kt * 16 + ak];
            Bs[ak][am + 16 * i] = K[(size_t)(am + 16 * i) * Hh + kt * 16 + ak];
        }
        __syncthreads();

#pragma unroll
        for (int k = 0; k < 16; k++) {
            float a[8], bb[8];
            *(float4*)&a[0]  = *(const float4*)&As[k][ty * 8];
            *(float4*)&a[4]  = *(const float4*)&As[k][ty * 8 + 4];
            *(float4*)&bb[0] = *(const float4*)&Bs[k][tx * 8];
            *(float4*)&bb[4] = *(const float4*)&Bs[k][tx * 8 + 4];
#pragma unroll
            for (int i = 0; i < 8; i++)
#pragma unroll
                for (int j = 0; j < 8; j++)
                    c[i][j] += a[i] * bb[j];
        }
    }
    __syncthreads();

    // Softmax over t. Row s = ty*8+i lives on the 16 lanes sharing ty
    // (tid = ty*16+tx => contiguous, 16-aligned lane group inside one warp).
    const float scale = 1.0f / sqrtf((float)Hh);
#pragma unroll
    for (int i = 0; i < 8; i++) {
        float m = -1e30f;
#pragma unroll
        for (int j = 0; j < 8; j++) {
            c[i][j] *= scale;
            m = fmaxf(m, c[i][j]);
        }
#pragma unroll
        for (int o = 1; o < 16; o <<= 1)
            m = fmaxf(m, __shfl_xor_sync(0xffffffffu, m, o));
        float s = 0.0f;
#pragma unroll
        for (int j = 0; j < 8; j++) {
            c[i][j] = __expf(c[i][j] - m);
            s += c[i][j];
        }
#pragma unroll
        for (int o = 1; o < 16; o <<= 1)
            s += __shfl_xor_sync(0xffffffffu, s, o);
        float inv = 1.0f / s;
#pragma unroll
        for (int j = 0; j < 8; j++) c[i][j] *= inv;
    }

    // Column sums -> pbar (sum over s of P[s,t])
#pragma unroll
    for (int j = 0; j < 8; j++) {
        float cs = 0.0f;
#pragma unroll
        for (int i = 0; i < 8; i++) cs += c[i][j];
        atomicAdd(&pbar[tx * 8 + j], cs);
    }
    __syncthreads();

    // ctx[h] = (1/S) * sum_t pbar[t] * V[t,h]; each thread owns 3 h values
    float acc0 = 0.0f, acc1 = 0.0f, acc2 = 0.0f;
#pragma unroll 4
    for (int t = 0; t < Ss; t++) {
        float p = pbar[t];
        const float* vr = V + (size_t)t * Hh + tid;
        acc0 += p * vr[0];
        acc1 += p * vr[256];
        acc2 += p * vr[512];
    }
    const float invS = 1.0f / (float)Ss;
    acc0 *= invS; acc1 *= invS; acc2 *= invS;

    // LayerNorm over 768
    float lsum = acc0 + acc1 + acc2;
    float lsq  = acc0 * acc0 + acc1 * acc1 + acc2 * acc2;
    float tot  = block_reduce_sum(lsum, red);
    float tot2 = block_reduce_sum(lsq, red);
    const float mu  = tot * (1.0f / (float)Hh);
    const float var = tot2 * (1.0f / (float)Hh) - mu * mu;
    const float rstd = rsqrtf(var + LN_EPS);

    // g2l partial: cls_fc[e,h] * ln(ctx[h]);  g2g partial: mcls[b,d]*ecls[e,d]
    const float* __restrict__ cfc = g_c + (size_t)e * Hh;
    float p1 = 0.0f;
    {
        int h = tid;
        float x = (acc0 - mu) * rstd * lng[h] + lnb[h];
        p1 += cfc[h] * x;
        h = tid + 256;
        x = (acc1 - mu) * rstd * lng[h] + lnb[h];
        p1 += cfc[h] * x;
        h = tid + 512;
        x = (acc2 - mu) * rstd * lng[h] + lnb[h];
        p1 += cfc[h] * x;
    }
    float p2 = 0.0f;
    {
        const float* mr = mcls + (size_t)b * Dd;
        const float* er = ecls + (size_t)e * Dd;
        p2 += mr[tid] * er[tid];
        p2 += mr[tid + 256] * er[tid + 256];
        p2 += mr[tid + 512] * er[tid + 512];
    }
    float g2l = block_reduce_sum(p1, red);
    float g2g = block_reduce_sum(p2, red);
    if (tid == 0) out[(size_t)b * Ee + e] = 0.5f * (g2l + g2g);
}

// ---------------------------------------------------------------------------
extern "C" void kernel_launch(void* const* d_in, const int* in_sizes, int n_in,
                              void* d_out, int out_size)
{
    const float* ecls = (const float*)d_in[0];   // [E, D]
    const float* etok = (const float*)d_in[1];   // [E, S, D]
    const float* mcls = (const float*)d_in[2];   // [B, D]
    const float* mtok = (const float*)d_in[3];   // [B, S, D]
    const float* Wq = (const float*)d_in[4];
    const float* bq = (const float*)d_in[5];
    const float* Wk = (const float*)d_in[6];
    const float* bk = (const float*)d_in[7];
    const float* Wv = (const float*)d_in[8];
    const float* bv = (const float*)d_in[9];
    const float* Wc = (const float*)d_in[10];
    const float* bc = (const float*)d_in[11];
    const float* lng = (const float*)d_in[12];
    const float* lnb = (const float*)d_in[13];
    float* out = (float*)d_out;

    float *q_ptr, *k_ptr, *v_ptr, *c_ptr;
    cudaGetSymbolAddress((void**)&q_ptr, g_q);
    cudaGetSymbolAddress((void**)&k_ptr, g_k);
    cudaGetSymbolAddress((void**)&v_ptr, g_v);
    cudaGetSymbolAddress((void**)&c_ptr, g_c);

    dim3 blk(256);
    proj_kernel<<<dim3(Hh / 128, (Ee * Ss) / 128), blk>>>(etok, Wq, bq, q_ptr);
    proj_kernel<<<dim3(Hh / 128, (Bb * Ss) / 128), blk>>>(mtok, Wk, bk, k_ptr);
    proj_kernel<<<dim3(Hh / 128, (Bb * Ss) / 128), blk>>>(mtok, Wv, bv, v_ptr);
    proj_kernel<<<dim3(Hh / 128, Ee / 128), blk>>>(ecls, Wc, bc, c_ptr);

    attn_kernel<<<dim3(Ee * Bb), blk>>>(ecls, mcls, lng, lnb, out);
}

// round 6
// speedup vs baseline: 2.7550x; 2.7550x over previous
#include <cuda_runtime.h>
#include <cstdint>
#include <math.h>

#define Dd 768
#define Hh 768
#define Ee 128
#define Bb 32
#define Ss 128
#define LN_EPS 1e-5f

// Scratch (static device arrays are allowed)
__device__ float g_q[Ee * Ss * Hh];
__device__ float g_k[Bb * Ss * Hh];
__device__ float g_v[Bb * Ss * Hh];
__device__ float g_c[Ee * Hh];

// ---------------------------------------------------------------------------
// helpers
// ---------------------------------------------------------------------------
__device__ __forceinline__ uint32_t f2tf(float x) {
    uint32_t r;
    asm("cvt.rna.tf32.f32 %0, %1;" : "=r"(r) : "f"(x));
    return r;
}

__device__ __forceinline__ void mma_tf32(float* c, const uint32_t* a,
                                         uint32_t b0, uint32_t b1) {
    asm volatile(
        "mma.sync.aligned.m16n8k8.row.col.f32.tf32.tf32.f32 "
        "{%0,%1,%2,%3}, {%4,%5,%6,%7}, {%8,%9}, {%0,%1,%2,%3};\n"
        : "+f"(c[0]), "+f"(c[1]), "+f"(c[2]), "+f"(c[3])
        : "r"(a[0]), "r"(a[1]), "r"(a[2]), "r"(a[3]), "r"(b0), "r"(b1));
}

// block reduction, 256 threads
__device__ __forceinline__ float brsum(float v, float* red, int tid) {
#pragma unroll
    for (int o = 16; o > 0; o >>= 1) v += __shfl_xor_sync(0xffffffffu, v, o);
    if ((tid & 31) == 0) red[tid >> 5] = v;
    __syncthreads();
    if (tid < 8) {
        float r = red[tid];
#pragma unroll
        for (int o = 4; o > 0; o >>= 1) r += __shfl_xor_sync(0x000000ffu, r, o);
        if (tid == 0) red[0] = r;
    }
    __syncthreads();
    v = red[0];
    __syncthreads();
    return v;
}

// ---------------------------------------------------------------------------
// Projection: Y[M,768] = X[M,768] @ W[768,768] + bias via tf32 mma.sync
// grid (6, M/128), 256 threads (8 warps: 4 x M, 2 x N), warp tile 32x64
// smem: As[128][36] u32 (tf32), Bs[32][132] u32
// ---------------------------------------------------------------------------
#define BS_STRIDE 132
#define PROJ_SMEM (1024 + 128 * 36 * 4 + 32 * BS_STRIDE * 4)

__global__ __launch_bounds__(256)
void proj_mma(const float* __restrict__ X, const float* __restrict__ W,
              const float* __restrict__ bias, float* __restrict__ Y)
{
    extern __shared__ char smem[];
    uint32_t* As = (uint32_t*)(smem + 1024);            // [128][36]
    uint32_t* Bs = As + 128 * 36;                       // [32][132]

    const int tid = threadIdx.x;
    const int wid = tid >> 5;
    const int lane = tid & 31;
    const int gid = lane >> 2;
    const int tg = lane & 3;
    const int wm = wid & 3;
    const int wn = wid >> 2;
    const int n0 = blockIdx.x << 7;
    const int m0 = blockIdx.y << 7;

    float c[2][8][4];
#pragma unroll
    for (int mt = 0; mt < 2; mt++)
#pragma unroll
        for (int nt = 0; nt < 8; nt++)
#pragma unroll
            for (int q = 0; q < 4; q++) c[mt][nt][q] = 0.0f;

    for (int kt = 0; kt < Dd / 32; ++kt) {
        // A tile: 128 rows x 32 cols
#pragma unroll
        for (int it = 0; it < 4; ++it) {
            int idx = tid + (it << 8);
            int r = idx >> 3, c4 = (idx & 7) << 2;
            float4 v = *(const float4*)&X[(size_t)(m0 + r) * Dd + kt * 32 + c4];
            uint4 u = {f2tf(v.x), f2tf(v.y), f2tf(v.z), f2tf(v.w)};
            *(uint4*)&As[r * 36 + c4] = u;
        }
        // B tile: W rows kt*32..+31, cols n0..n0+127 -> Bs[k][n]
#pragma unroll
        for (int it = 0; it < 4; ++it) {
            int idx = tid + (it << 8);
            int kk = idx >> 5, n4 = (idx & 31) << 2;
            float4 v = *(const float4*)&W[(size_t)(kt * 32 + kk) * Hh + n0 + n4];
            uint4 u = {f2tf(v.x), f2tf(v.y), f2tf(v.z), f2tf(v.w)};
            *(uint4*)&Bs[kk * BS_STRIDE + n4] = u;
        }
        __syncthreads();

#pragma unroll
        for (int ks = 0; ks < 4; ++ks) {
            int k0 = ks << 3;
            uint32_t a[2][4];
#pragma unroll
            for (int mt = 0; mt < 2; mt++) {
                int r = wm * 32 + mt * 16 + gid;
                a[mt][0] = As[r * 36 + k0 + tg];
                a[mt][1] = As[(r + 8) * 36 + k0 + tg];
                a[mt][2] = As[r * 36 + k0 + tg + 4];
                a[mt][3] = As[(r + 8) * 36 + k0 + tg + 4];
            }
#pragma unroll
            for (int nt = 0; nt < 8; nt++) {
                int n = wn * 64 + nt * 8 + gid;
                uint32_t b0 = Bs[(k0 + tg) * BS_STRIDE + n];
                uint32_t b1 = Bs[(k0 + tg + 4) * BS_STRIDE + n];
                mma_tf32(c[0][nt], a[0], b0, b1);
                mma_tf32(c[1][nt], a[1], b0, b1);
            }
        }
        __syncthreads();
    }

    // epilogue: bias + store (float2 per row pair)
#pragma unroll
    for (int nt = 0; nt < 8; nt++) {
        int col = n0 + wn * 64 + nt * 8 + 2 * tg;
        float2 bv = *(const float2*)&bias[col];
#pragma unroll
        for (int mt = 0; mt < 2; mt++) {
            int r = m0 + wm * 32 + mt * 16 + gid;
            float2 o0 = {c[mt][nt][0] + bv.x, c[mt][nt][1] + bv.y};
            float2 o1 = {c[mt][nt][2] + bv.x, c[mt][nt][3] + bv.y};
            *(float2*)&Y[(size_t)r * Hh + col] = o0;
            *(float2*)&Y[(size_t)(r + 8) * Hh + col] = o1;
        }
    }
}

// ---------------------------------------------------------------------------
// Fused attention: one CTA per (e,b), 256 threads (8 warps 4x2).
//   scores = Q_e @ K_b^T (tf32 mma.sync, 128x128x768)
//   softmax (2 threads/row), pbar col-sums, ctx=pbar@V/S, LN, dual score
// smem: pbar[128], red[8], then overlay { As[128][36] + Ks[128][36] u32 }
//       / P[128][129] fp32
// ---------------------------------------------------------------------------
#define OFF_TILE 1024
#define ATTN_SMEM (1024 + 128 * 129 * 4)

__global__ __launch_bounds__(256)
void attn_mma(const float* __restrict__ ecls, const float* __restrict__ mcls,
              const float* __restrict__ lng, const float* __restrict__ lnb,
              float* __restrict__ out)
{
    extern __shared__ char smem[];
    float* pbar = (float*)smem;                 // [128]
    float* red = (float*)(smem + 512);          // [8]
    uint32_t* As = (uint32_t*)(smem + OFF_TILE);        // [128][36]
    uint32_t* Ks = As + 128 * 36;                       // [128][36]
    float* P = (float*)(smem + OFF_TILE);               // [128][129] overlay

    const int tid = threadIdx.x;
    const int wid = tid >> 5;
    const int lane = tid & 31;
    const int gid = lane >> 2;
    const int tg = lane & 3;
    const int wm = wid & 3;
    const int wn = wid >> 2;
    const int e = blockIdx.x >> 5;
    const int b = blockIdx.x & 31;

    const float* __restrict__ Q = g_q + (size_t)e * Ss * Hh;
    const float* __restrict__ K = g_k + (size_t)b * Ss * Hh;
    const float* __restrict__ V = g_v + (size_t)b * Ss * Hh;

    float c[2][8][4];
#pragma unroll
    for (int mt = 0; mt < 2; mt++)
#pragma unroll
        for (int nt = 0; nt < 8; nt++)
#pragma unroll
            for (int q = 0; q < 4; q++) c[mt][nt][q] = 0.0f;

    for (int kt = 0; kt < Hh / 32; ++kt) {
#pragma unroll
        for (int it = 0; it < 4; ++it) {
            int idx = tid + (it << 8);
            int r = idx >> 3, c4 = (idx & 7) << 2;
            float4 q4 = *(const float4*)&Q[(size_t)r * Hh + kt * 32 + c4];
            uint4 qu = {f2tf(q4.x), f2tf(q4.y), f2tf(q4.z), f2tf(q4.w)};
            *(uint4*)&As[r * 36 + c4] = qu;
            float4 k4 = *(const float4*)&K[(size_t)r * Hh + kt * 32 + c4];
            uint4 ku = {f2tf(k4.x), f2tf(k4.y), f2tf(k4.z), f2tf(k4.w)};
            *(uint4*)&Ks[r * 36 + c4] = ku;
        }
        __syncthreads();

#pragma unroll
        for (int ks = 0; ks < 4; ++ks) {
            int k0 = ks << 3;
            uint32_t a[2][4];
#pragma unroll
            for (int mt = 0; mt < 2; mt++) {
                int r = wm * 32 + mt * 16 + gid;
                a[mt][0] = As[r * 36 + k0 + tg];
                a[mt][1] = As[(r + 8) * 36 + k0 + tg];
                a[mt][2] = As[r * 36 + k0 + tg + 4];
                a[mt][3] = As[(r + 8) * 36 + k0 + tg + 4];
            }
#pragma unroll
            for (int nt = 0; nt < 8; nt++) {
                int n = wn * 64 + nt * 8 + gid;
                uint32_t b0 = Ks[n * 36 + k0 + tg];
                uint32_t b1 = Ks[n * 36 + k0 + tg + 4];
                mma_tf32(c[0][nt], a[0], b0, b1);
                mma_tf32(c[1][nt], a[1], b0, b1);
            }
        }
        __syncthreads();
    }

    // fragments -> P (raw scores)
#pragma unroll
    for (int nt = 0; nt < 8; nt++) {
        int col = wn * 64 + nt * 8 + 2 * tg;
#pragma unroll
        for (int mt = 0; mt < 2; mt++) {
            int r = wm * 32 + mt * 16 + gid;
            P[r * 129 + col] = c[mt][nt][0];
            P[r * 129 + col + 1] = c[mt][nt][1];
            P[(r + 8) * 129 + col] = c[mt][nt][2];
            P[(r + 8) * 129 + col + 1] = c[mt][nt][3];
        }
    }
    __syncthreads();

    // softmax: 2 threads per row (halves combined via shfl xor 1)
    const float scale = 0.0360843918243516f;  // 1/sqrt(768)
    {
        int row = tid >> 1, half = tid & 1;
        float* pr = &P[row * 129 + half * 64];
        float m = -1e30f;
#pragma unroll 8
        for (int j = 0; j < 64; ++j) m = fmaxf(m, pr[j]);
        m = fmaxf(m, __shfl_xor_sync(0xffffffffu, m, 1));
        float s = 0.0f;
#pragma unroll 8
        for (int j = 0; j < 64; ++j) {
            float v = __expf((pr[j] - m) * scale);
            pr[j] = v;
            s += v;
        }
        s += __shfl_xor_sync(0xffffffffu, s, 1);
        float inv = 1.0f / s;
#pragma unroll 8
        for (int j = 0; j < 64; ++j) pr[j] *= inv;
    }
    __syncthreads();

    // pbar[t] = sum_s P[s][t]
    if (tid < 128) {
        float cs = 0.0f;
#pragma unroll 8
        for (int s = 0; s < 128; ++s) cs += P[s * 129 + tid];
        pbar[tid] = cs;
    }
    __syncthreads();

    // ctx[h] = (1/S) * sum_t pbar[t] * V[t,h]; each thread owns 3 h values
    float acc0 = 0.0f, acc1 = 0.0f, acc2 = 0.0f;
#pragma unroll 4
    for (int t = 0; t < Ss; t++) {
        float p = pbar[t];
        const float* vr = V + (size_t)t * Hh + tid;
        acc0 += p * vr[0];
        acc1 += p * vr[256];
        acc2 += p * vr[512];
    }
    const float invS = 1.0f / (float)Ss;
    acc0 *= invS; acc1 *= invS; acc2 *= invS;

    // LayerNorm over 768
    float lsum = acc0 + acc1 + acc2;
    float lsq = acc0 * acc0 + acc1 * acc1 + acc2 * acc2;
    float tot = brsum(lsum, red, tid);
    float tot2 = brsum(lsq, red, tid);
    const float mu = tot * (1.0f / (float)Hh);
    const float var = tot2 * (1.0f / (float)Hh) - mu * mu;
    const float rstd = rsqrtf(var + LN_EPS);

    // g2l partial + g2g partial
    const float* __restrict__ cfc = g_c + (size_t)e * Hh;
    float p1 = 0.0f;
    {
        int h = tid;
        float x = (acc0 - mu) * rstd * lng[h] + lnb[h];
        p1 += cfc[h] * x;
        h = tid + 256;
        x = (acc1 - mu) * rstd * lng[h] + lnb[h];
        p1 += cfc[h] * x;
        h = tid + 512;
        x = (acc2 - mu) * rstd * lng[h] + lnb[h];
        p1 += cfc[h] * x;
    }
    float p2 = 0.0f;
    {
        const float* mr = mcls + (size_t)b * Dd;
        const float* er = ecls + (size_t)e * Dd;
        p2 += mr[tid] * er[tid];
        p2 += mr[tid + 256] * er[tid + 256];
        p2 += mr[tid + 512] * er[tid + 512];
    }
    float g2l = brsum(p1, red, tid);
    float g2g = brsum(p2, red, tid);
    if (tid == 0) out[(size_t)b * Ee + e] = 0.5f * (g2l + g2g);
}

// ---------------------------------------------------------------------------
extern "C" void kernel_launch(void* const* d_in, const int* in_sizes, int n_in,
                              void* d_out, int out_size)
{
    const float* ecls = (const float*)d_in[0];
    const float* etok = (const float*)d_in[1];
    const float* mcls = (const float*)d_in[2];
    const float* mtok = (const float*)d_in[3];
    const float* Wq = (const float*)d_in[4];
    const float* bq = (const float*)d_in[5];
    const float* Wk = (const float*)d_in[6];
    const float* bk = (const float*)d_in[7];
    const float* Wv = (const float*)d_in[8];
    const float* bv = (const float*)d_in[9];
    const float* Wc = (const float*)d_in[10];
    const float* bc = (const float*)d_in[11];
    const float* lng = (const float*)d_in[12];
    const float* lnb = (const float*)d_in[13];
    float* out = (float*)d_out;

    float *q_ptr, *k_ptr, *v_ptr, *c_ptr;
    cudaGetSymbolAddress((void**)&q_ptr, g_q);
    cudaGetSymbolAddress((void**)&k_ptr, g_k);
    cudaGetSymbolAddress((void**)&v_ptr, g_v);
    cudaGetSymbolAddress((void**)&c_ptr, g_c);

    cudaFuncSetAttribute(proj_mma, cudaFuncAttributeMaxDynamicSharedMemorySize, PROJ_SMEM);
    cudaFuncSetAttribute(attn_mma, cudaFuncAttributeMaxDynamicSharedMemorySize, ATTN_SMEM);

    proj_mma<<<dim3(Hh / 128, (Ee * Ss) / 128), 256, PROJ_SMEM>>>(etok, Wq, bq, q_ptr);
    proj_mma<<<dim3(Hh / 128, (Bb * Ss) / 128), 256, PROJ_SMEM>>>(mtok, Wk, bk, k_ptr);
    proj_mma<<<dim3(Hh / 128, (Bb * Ss) / 128), 256, PROJ_SMEM>>>(mtok, Wv, bv, v_ptr);
    proj_mma<<<dim3(Hh / 128, 1), 256, PROJ_SMEM>>>(ecls, Wc, bc, c_ptr);

    attn_mma<<<dim3(Ee * Bb), 256, ATTN_SMEM>>>(ecls, mcls, lng, lnb, out);
}

// round 7
// speedup vs baseline: 3.2791x; 1.1902x over previous
#include <cuda_runtime.h>
#include <cstdint>
#include <math.h>

#define Dd 768
#define Hh 768
#define Ee 128
#define Bb 32
#define Ss 128
#define LN_EPS 1e-5f

// Scratch (static device arrays are allowed)
__device__ float g_q[Ee * Ss * Hh];   // pre-rounded tf32 values (bit patterns)
__device__ float g_k[Bb * Ss * Hh];   // pre-rounded tf32 values
__device__ float g_v[Bb * Ss * Hh];   // exact fp32
__device__ float g_c[Ee * Hh];        // exact fp32

// ---------------------------------------------------------------------------
// helpers
// ---------------------------------------------------------------------------
__device__ __forceinline__ uint32_t f2tf(float x) {
    uint32_t r;
    asm("cvt.rna.tf32.f32 %0, %1;" : "=r"(r) : "f"(x));
    return r;
}

__device__ __forceinline__ uint32_t smem_u32(const void* p) {
    uint32_t a;
    asm("{ .reg .u64 t; cvta.to.shared.u64 t, %1; cvt.u32.u64 %0, t; }"
        : "=r"(a) : "l"(p));
    return a;
}

__device__ __forceinline__ void cp16(uint32_t dst, const void* src) {
    asm volatile("cp.async.ca.shared.global [%0], [%1], 16;"
                 :: "r"(dst), "l"(src));
}
#define CP_COMMIT() asm volatile("cp.async.commit_group;" ::: "memory")
#define CP_WAIT1()  asm volatile("cp.async.wait_group 1;" ::: "memory")

__device__ __forceinline__ void mma_tf32(float* c, const uint32_t* a,
                                         uint32_t b0, uint32_t b1) {
    asm volatile(
        "mma.sync.aligned.m16n8k8.row.col.f32.tf32.tf32.f32 "
        "{%0,%1,%2,%3}, {%4,%5,%6,%7}, {%8,%9}, {%0,%1,%2,%3};\n"
        : "+f"(c[0]), "+f"(c[1]), "+f"(c[2]), "+f"(c[3])
        : "r"(a[0]), "r"(a[1]), "r"(a[2]), "r"(a[3]), "r"(b0), "r"(b1));
}

// block reduction, 256 threads
__device__ __forceinline__ float brsum(float v, float* red, int tid) {
#pragma unroll
    for (int o = 16; o > 0; o >>= 1) v += __shfl_xor_sync(0xffffffffu, v, o);
    if ((tid & 31) == 0) red[tid >> 5] = v;
    __syncthreads();
    if (tid < 8) {
        float r = red[tid];
#pragma unroll
        for (int o = 4; o > 0; o >>= 1) r += __shfl_xor_sync(0x000000ffu, r, o);
        if (tid == 0) red[0] = r;
    }
    __syncthreads();
    v = red[0];
    __syncthreads();
    return v;
}

// ---------------------------------------------------------------------------
// Merged projection: all 4 GEMMs in one launch.
// grid (6, 193): by in [0,128) q | [128,160) k | [160,192) v | 192 cls
// 256 threads (8 warps: 4 x M, 2 x N), warp tile 32x64, BK=32,
// register-staged prefetch, cvt.rna at smem store.
// smem: As[128][36] u32, Bs[32][132] u32
// ---------------------------------------------------------------------------
#define BS_STRIDE 132
#define PROJ_SMEM (1024 + 128 * 36 * 4 + 32 * BS_STRIDE * 4)

__global__ __launch_bounds__(256)
void proj_mma(const float* __restrict__ etok, const float* __restrict__ mtok,
              const float* __restrict__ ecls,
              const float* __restrict__ Wq, const float* __restrict__ bq,
              const float* __restrict__ Wk, const float* __restrict__ bk,
              const float* __restrict__ Wv, const float* __restrict__ bv,
              const float* __restrict__ Wc, const float* __restrict__ bc,
              float* __restrict__ Yq, float* __restrict__ Yk,
              float* __restrict__ Yv, float* __restrict__ Yc)
{
    extern __shared__ char smem[];
    uint32_t* As = (uint32_t*)(smem + 1024);            // [128][36]
    uint32_t* Bs = As + 128 * 36;                       // [32][132]

    const int tid = threadIdx.x;
    const int wid = tid >> 5;
    const int lane = tid & 31;
    const int gid = lane >> 2;
    const int tg = lane & 3;
    const int wm = wid & 3;
    const int wn = wid >> 2;
    const int n0 = blockIdx.x << 7;

    // segment select
    const int by = blockIdx.y;
    const float *X, *W, *bias;
    float* Y;
    int m0, rnd;
    if (by < 128)      { X = etok; W = Wq; bias = bq; Y = Yq; m0 = by << 7;        rnd = 1; }
    else if (by < 160) { X = mtok; W = Wk; bias = bk; Y = Yk; m0 = (by - 128) << 7; rnd = 1; }
    else if (by < 192) { X = mtok; W = Wv; bias = bv; Y = Yv; m0 = (by - 160) << 7; rnd = 0; }
    else               { X = ecls; W = Wc; bias = bc; Y = Yc; m0 = 0;               rnd = 0; }

    float c[2][8][4];
#pragma unroll
    for (int mt = 0; mt < 2; mt++)
#pragma unroll
        for (int nt = 0; nt < 8; nt++)
#pragma unroll
            for (int q = 0; q < 4; q++) c[mt][nt][q] = 0.0f;

    float4 ra[4], rb[4];
    // preload chunk 0
#pragma unroll
    for (int it = 0; it < 4; ++it) {
        int idx = tid + (it << 8);
        int r = idx >> 3, c4 = (idx & 7) << 2;
        ra[it] = *(const float4*)&X[(size_t)(m0 + r) * Dd + c4];
        int kk = idx >> 5, n4 = (idx & 31) << 2;
        rb[it] = *(const float4*)&W[(size_t)kk * Hh + n0 + n4];
    }

    for (int kt = 0; kt < Dd / 32; ++kt) {
        // store staged tiles (cvt.rna -> tf32)
#pragma unroll
        for (int it = 0; it < 4; ++it) {
            int idx = tid + (it << 8);
            int r = idx >> 3, c4 = (idx & 7) << 2;
            uint4 u = {f2tf(ra[it].x), f2tf(ra[it].y), f2tf(ra[it].z), f2tf(ra[it].w)};
            *(uint4*)&As[r * 36 + c4] = u;
            int kk = idx >> 5, n4 = (idx & 31) << 2;
            uint4 v = {f2tf(rb[it].x), f2tf(rb[it].y), f2tf(rb[it].z), f2tf(rb[it].w)};
            *(uint4*)&Bs[kk * BS_STRIDE + n4] = v;
        }
        __syncthreads();

        // prefetch next chunk while computing this one
        if (kt + 1 < Dd / 32) {
#pragma unroll
            for (int it = 0; it < 4; ++it) {
                int idx = tid + (it << 8);
                int r = idx >> 3, c4 = (idx & 7) << 2;
                ra[it] = *(const float4*)&X[(size_t)(m0 + r) * Dd + (kt + 1) * 32 + c4];
                int kk = idx >> 5, n4 = (idx & 31) << 2;
                rb[it] = *(const float4*)&W[(size_t)((kt + 1) * 32 + kk) * Hh + n0 + n4];
            }
        }

#pragma unroll
        for (int ks = 0; ks < 4; ++ks) {
            int k0 = ks << 3;
            uint32_t a[2][4];
#pragma unroll
            for (int mt = 0; mt < 2; mt++) {
                int r = wm * 32 + mt * 16 + gid;
                a[mt][0] = As[r * 36 + k0 + tg];
                a[mt][1] = As[(r + 8) * 36 + k0 + tg];
                a[mt][2] = As[r * 36 + k0 + tg + 4];
                a[mt][3] = As[(r + 8) * 36 + k0 + tg + 4];
            }
#pragma unroll
            for (int nt = 0; nt < 8; nt++) {
                int n = wn * 64 + nt * 8 + gid;
                uint32_t b0 = Bs[(k0 + tg) * BS_STRIDE + n];
                uint32_t b1 = Bs[(k0 + tg + 4) * BS_STRIDE + n];
                mma_tf32(c[0][nt], a[0], b0, b1);
                mma_tf32(c[1][nt], a[1], b0, b1);
            }
        }
        __syncthreads();
    }

    // epilogue: bias + (optional tf32 pre-round) + store
#pragma unroll
    for (int nt = 0; nt < 8; nt++) {
        int col = n0 + wn * 64 + nt * 8 + 2 * tg;
        float2 bv = *(const float2*)&bias[col];
#pragma unroll
        for (int mt = 0; mt < 2; mt++) {
            int r = m0 + wm * 32 + mt * 16 + gid;
            float2 o0 = {c[mt][nt][0] + bv.x, c[mt][nt][1] + bv.y};
            float2 o1 = {c[mt][nt][2] + bv.x, c[mt][nt][3] + bv.y};
            if (rnd) {
                o0.x = __uint_as_float(f2tf(o0.x));
                o0.y = __uint_as_float(f2tf(o0.y));
                o1.x = __uint_as_float(f2tf(o1.x));
                o1.y = __uint_as_float(f2tf(o1.y));
            }
            *(float2*)&Y[(size_t)r * Hh + col] = o0;
            *(float2*)&Y[(size_t)(r + 8) * Hh + col] = o1;
        }
    }
}

// ---------------------------------------------------------------------------
// Fused attention: one CTA per (e,b), 256 threads (8 warps 4x2).
//   Q/K already tf32-rounded -> cp.async raw bytes, 2-stage pipeline.
//   scores = Q_e @ K_b^T; softmax; pbar; ctx=pbar@V/S; LN; dual score
// smem: pbar[128] @0, red[8] @512,
//       tiles @1024: stage s at s*36864 { Q[128][36], K[128][36] u32 }
//       P[128][129] fp32 overlays tiles after mainloop
// ---------------------------------------------------------------------------
#define TILE_BYTES (128 * 36 * 4)          // 18432
#define STAGE_BYTES (2 * TILE_BYTES)       // 36864
#define OFF_TILE 1024
#define ATTN_SMEM (OFF_TILE + 2 * STAGE_BYTES)

__global__ __launch_bounds__(256, 2)
void attn_mma(const float* __restrict__ ecls, const float* __restrict__ mcls,
              const float* __restrict__ lng, const float* __restrict__ lnb,
              float* __restrict__ out)
{
    extern __shared__ char smem[];
    float* pbar = (float*)smem;                 // [128]
    float* red = (float*)(smem + 512);          // [8]
    float* P = (float*)(smem + OFF_TILE);       // [128][129] overlay

    const int tid = threadIdx.x;
    const int wid = tid >> 5;
    const int lane = tid & 31;
    const int gid = lane >> 2;
    const int tg = lane & 3;
    const int wm = wid & 3;
    const int wn = wid >> 2;
    const int e = blockIdx.x >> 5;
    const int b = blockIdx.x & 31;

    const float* __restrict__ Q = g_q + (size_t)e * Ss * Hh;
    const float* __restrict__ K = g_k + (size_t)b * Ss * Hh;
    const float* __restrict__ V = g_v + (size_t)b * Ss * Hh;

    const uint32_t stile = smem_u32(smem) + OFF_TILE;

    float c[2][8][4];
#pragma unroll
    for (int mt = 0; mt < 2; mt++)
#pragma unroll
        for (int nt = 0; nt < 8; nt++)
#pragma unroll
            for (int q = 0; q < 4; q++) c[mt][nt][q] = 0.0f;

    // issue cp.async for chunk kt into stage s
    auto issue = [&](int kt, int s) {
        uint32_t qb = stile + s * STAGE_BYTES;
        uint32_t kb = qb + TILE_BYTES;
#pragma unroll
        for (int it = 0; it < 4; ++it) {
            int idx = tid + (it << 8);
            int r = idx >> 3, c4 = (idx & 7) << 2;
            uint32_t off = (uint32_t)(r * 36 + c4) * 4;
            const float* gq = &Q[(size_t)r * Hh + kt * 32 + c4];
            const float* gk = &K[(size_t)r * Hh + kt * 32 + c4];
            cp16(qb + off, gq);
            cp16(kb + off, gk);
        }
    };

    issue(0, 0);
    CP_COMMIT();

    const int NKT = Hh / 32;  // 24
    for (int kt = 0; kt < NKT; ++kt) {
        if (kt + 1 < NKT) issue(kt + 1, (kt + 1) & 1);
        CP_COMMIT();
        CP_WAIT1();
        __syncthreads();

        const uint32_t* Qs = (const uint32_t*)(smem + OFF_TILE + (kt & 1) * STAGE_BYTES);
        const uint32_t* Ks = Qs + 128 * 36;

#pragma unroll
        for (int ks = 0; ks < 4; ++ks) {
            int k0 = ks << 3;
            uint32_t a[2][4];
#pragma unroll
            for (int mt = 0; mt < 2; mt++) {
                int r = wm * 32 + mt * 16 + gid;
                a[mt][0] = Qs[r * 36 + k0 + tg];
                a[mt][1] = Qs[(r + 8) * 36 + k0 + tg];
                a[mt][2] = Qs[r * 36 + k0 + tg + 4];
                a[mt][3] = Qs[(r + 8) * 36 + k0 + tg + 4];
            }
#pragma unroll
            for (int nt = 0; nt < 8; nt++) {
                int n = wn * 64 + nt * 8 + gid;
                uint32_t b0 = Ks[n * 36 + k0 + tg];
                uint32_t b1 = Ks[n * 36 + k0 + tg + 4];
                mma_tf32(c[0][nt], a[0], b0, b1);
                mma_tf32(c[1][nt], a[1], b0, b1);
            }
        }
        __syncthreads();
    }

    // fragments -> P (raw scores)
#pragma unroll
    for (int nt = 0; nt < 8; nt++) {
        int col = wn * 64 + nt * 8 + 2 * tg;
#pragma unroll
        for (int mt = 0; mt < 2; mt++) {
            int r = wm * 32 + mt * 16 + gid;
            P[r * 129 + col] = c[mt][nt][0];
            P[r * 129 + col + 1] = c[mt][nt][1];
            P[(r + 8) * 129 + col] = c[mt][nt][2];
            P[(r + 8) * 129 + col + 1] = c[mt][nt][3];
        }
    }
    __syncthreads();

    // softmax: 2 threads per row (halves combined via shfl xor 1)
    const float scale = 0.0360843918243516f;  // 1/sqrt(768)
    {
        int row = tid >> 1, half = tid & 1;
        float* pr = &P[row * 129 + half * 64];
        float m = -1e30f;
#pragma unroll 8
        for (int j = 0; j < 64; ++j) m = fmaxf(m, pr[j]);
        m = fmaxf(m, __shfl_xor_sync(0xffffffffu, m, 1));
        float s = 0.0f;
#pragma unroll 8
        for (int j = 0; j < 64; ++j) {
            float v = __expf((pr[j] - m) * scale);
            pr[j] = v;
            s += v;
        }
        s += __shfl_xor_sync(0xffffffffu, s, 1);
        float inv = 1.0f / s;
#pragma unroll 8
        for (int j = 0; j < 64; ++j) pr[j] *= inv;
    }
    __syncthreads();

    // pbar[t] = sum_s P[s][t]
    if (tid < 128) {
        float cs = 0.0f;
#pragma unroll 8
        for (int s = 0; s < 128; ++s) cs += P[s * 129 + tid];
        pbar[tid] = cs;
    }
    __syncthreads();

    // ctx[h] = (1/S) * sum_t pbar[t] * V[t,h]; each thread owns 3 h values
    float acc0 = 0.0f, acc1 = 0.0f, acc2 = 0.0f;
#pragma unroll 4
    for (int t = 0; t < Ss; t++) {
        float p = pbar[t];
        const float* vr = V + (size_t)t * Hh + tid;
        acc0 += p * vr[0];
        acc1 += p * vr[256];
        acc2 += p * vr[512];
    }
    const float invS = 1.0f / (float)Ss;
    acc0 *= invS; acc1 *= invS; acc2 *= invS;

    // LayerNorm over 768
    float lsum = acc0 + acc1 + acc2;
    float lsq = acc0 * acc0 + acc1 * acc1 + acc2 * acc2;
    float tot = brsum(lsum, red, tid);
    float tot2 = brsum(lsq, red, tid);
    const float mu = tot * (1.0f / (float)Hh);
    const float var = tot2 * (1.0f / (float)Hh) - mu * mu;
    const float rstd = rsqrtf(var + LN_EPS);

    // g2l partial + g2g partial
    const float* __restrict__ cfc = g_c + (size_t)e * Hh;
    float p1 = 0.0f;
    {
        int h = tid;
        float x = (acc0 - mu) * rstd * lng[h] + lnb[h];
        p1 += cfc[h] * x;
        h = tid + 256;
        x = (acc1 - mu) * rstd * lng[h] + lnb[h];
        p1 += cfc[h] * x;
        h = tid + 512;
        x = (acc2 - mu) * rstd * lng[h] + lnb[h];
        p1 += cfc[h] * x;
    }
    float p2 = 0.0f;
    {
        const float* mr = mcls + (size_t)b * Dd;
        const float* er = ecls + (size_t)e * Dd;
        p2 += mr[tid] * er[tid];
        p2 += mr[tid + 256] * er[tid + 256];
        p2 += mr[tid + 512] * er[tid + 512];
    }
    float g2l = brsum(p1, red, tid);
    float g2g = brsum(p2, red, tid);
    if (tid == 0) out[(size_t)b * Ee + e] = 0.5f * (g2l + g2g);
}

// ---------------------------------------------------------------------------
extern "C" void kernel_launch(void* const* d_in, const int* in_sizes, int n_in,
                              void* d_out, int out_size)
{
    const float* ecls = (const float*)d_in[0];
    const float* etok = (const float*)d_in[1];
    const float* mcls = (const float*)d_in[2];
    const float* mtok = (const float*)d_in[3];
    const float* Wq = (const float*)d_in[4];
    const float* bq = (const float*)d_in[5];
    const float* Wk = (const float*)d_in[6];
    const float* bk = (const float*)d_in[7];
    const float* Wv = (const float*)d_in[8];
    const float* bv = (const float*)d_in[9];
    const float* Wc = (const float*)d_in[10];
    const float* bc = (const float*)d_in[11];
    const float* lng = (const float*)d_in[12];
    const float* lnb = (const float*)d_in[13];
    float* out = (float*)d_out;

    float *q_ptr, *k_ptr, *v_ptr, *c_ptr;
    cudaGetSymbolAddress((void**)&q_ptr, g_q);
    cudaGetSymbolAddress((void**)&k_ptr, g_k);
    cudaGetSymbolAddress((void**)&v_ptr, g_v);
    cudaGetSymbolAddress((void**)&c_ptr, g_c);

    cudaFuncSetAttribute(proj_mma, cudaFuncAttributeMaxDynamicSharedMemorySize, PROJ_SMEM);
    cudaFuncSetAttribute(attn_mma, cudaFuncAttributeMaxDynamicSharedMemorySize, ATTN_SMEM);

    proj_mma<<<dim3(Hh / 128, 193), 256, PROJ_SMEM>>>(
        etok, mtok, ecls, Wq, bq, Wk, bk, Wv, bv, Wc, bc,
        q_ptr, k_ptr, v_ptr, c_ptr);

    attn_mma<<<dim3(Ee * Bb), 256, ATTN_SMEM>>>(ecls, mcls, lng, lnb, out);
}

// round 8
// speedup vs baseline: 3.5520x; 1.0832x over previous
#include <cuda_runtime.h>
#include <cstdint>
#include <math.h>

#define Dd 768
#define Hh 768
#define Ee 128
#define Bb 32
#define Ss 128
#define LN_EPS 1e-5f

// Scratch (static device arrays are allowed)
__device__ float g_q[Ee * Ss * Hh];    // pre-rounded tf32 (bit patterns)
__device__ float g_k[Bb * Ss * Hh];    // pre-rounded tf32
__device__ float g_v[Bb * Ss * Hh];    // exact fp32
__device__ float g_c[Ee * Hh];         // exact fp32
// tf32-rounded copies of inputs (for cp.async proj pipeline)
__device__ float g_etok[Ee * Ss * Dd];
__device__ float g_mtok[Bb * Ss * Dd];
__device__ float g_ecls[Ee * Dd];
__device__ float g_wq[Dd * Hh];
__device__ float g_wk[Dd * Hh];
__device__ float g_wv[Dd * Hh];
__device__ float g_wc[Dd * Hh];

// ---------------------------------------------------------------------------
// helpers
// ---------------------------------------------------------------------------
__device__ __forceinline__ uint32_t f2tf(float x) {
    uint32_t r;
    asm("cvt.rna.tf32.f32 %0, %1;" : "=r"(r) : "f"(x));
    return r;
}

__device__ __forceinline__ uint32_t smem_u32(const void* p) {
    uint32_t a;
    asm("{ .reg .u64 t; cvta.to.shared.u64 t, %1; cvt.u32.u64 %0, t; }"
        : "=r"(a) : "l"(p));
    return a;
}

__device__ __forceinline__ void cp16(uint32_t dst, const void* src) {
    asm volatile("cp.async.ca.shared.global [%0], [%1], 16;"
                 :: "r"(dst), "l"(src));
}
#define CP_COMMIT() asm volatile("cp.async.commit_group;" ::: "memory")
#define CP_WAIT1()  asm volatile("cp.async.wait_group 1;" ::: "memory")

__device__ __forceinline__ void mma_tf32(float* c, const uint32_t* a,
                                         uint32_t b0, uint32_t b1) {
    asm volatile(
        "mma.sync.aligned.m16n8k8.row.col.f32.tf32.tf32.f32 "
        "{%0,%1,%2,%3}, {%4,%5,%6,%7}, {%8,%9}, {%0,%1,%2,%3};\n"
        : "+f"(c[0]), "+f"(c[1]), "+f"(c[2]), "+f"(c[3])
        : "r"(a[0]), "r"(a[1]), "r"(a[2]), "r"(a[3]), "r"(b0), "r"(b1));
}

// block reduction, 128 threads (4 warps)
__device__ __forceinline__ float brsum(float v, float* red, int tid) {
#pragma unroll
    for (int o = 16; o > 0; o >>= 1) v += __shfl_xor_sync(0xffffffffu, v, o);
    if ((tid & 31) == 0) red[tid >> 5] = v;
    __syncthreads();
    if (tid < 4) {
        float r = red[tid];
        r += __shfl_xor_sync(0x0000000fu, r, 1);
        r += __shfl_xor_sync(0x0000000fu, r, 2);
        if (tid == 0) red[0] = r;
    }
    __syncthreads();
    v = red[0];
    __syncthreads();
    return v;
}

// ---------------------------------------------------------------------------
// Pre-round pass: dst[i] = tf32_rna(src[i])  (float4 granularity)
// ---------------------------------------------------------------------------
__global__ __launch_bounds__(256)
void round_pre(const float* __restrict__ src, float* __restrict__ dst, int n4)
{
    int idx = blockIdx.x * 256 + threadIdx.x;
    if (idx < n4) {
        float4 v = ((const float4*)src)[idx];
        float4 o;
        o.x = __uint_as_float(f2tf(v.x));
        o.y = __uint_as_float(f2tf(v.y));
        o.z = __uint_as_float(f2tf(v.z));
        o.w = __uint_as_float(f2tf(v.w));
        ((float4*)dst)[idx] = o;
    }
}

// ---------------------------------------------------------------------------
// Merged projection: all 4 GEMMs, cp.async 2-stage pipeline.
// grid (6, 193): by in [0,128) q | [128,160) k | [160,192) v | 192 cls
// 128 threads (4 warps, 2M x 2N, warp tile 64x64), BK=32.
// smem per stage: As[128][36] u32 (18432 B) + Bs[32][132] u32 (16896 B)
// ---------------------------------------------------------------------------
#define A_TILE_B (128 * 36 * 4)
#define PB_TILE_B (32 * 132 * 4)
#define P_STAGE_B (A_TILE_B + PB_TILE_B)
#define PROJ_SMEM (1024 + 2 * P_STAGE_B)

__global__ __launch_bounds__(128, 2)
void proj_mma(const float* __restrict__ bq, const float* __restrict__ bk,
              const float* __restrict__ bv, const float* __restrict__ bc,
              float* __restrict__ Yq, float* __restrict__ Yk,
              float* __restrict__ Yv, float* __restrict__ Yc)
{
    extern __shared__ char smem[];

    const int tid = threadIdx.x;
    const int wid = tid >> 5;
    const int lane = tid & 31;
    const int gid = lane >> 2;
    const int tg = lane & 3;
    const int wm = wid & 1;
    const int wn = wid >> 1;
    const int n0 = blockIdx.x << 7;

    // segment select (rounded input copies)
    const int by = blockIdx.y;
    const float *X, *W, *bias;
    float* Y;
    int m0, rnd;
    if (by < 128)      { X = g_etok; W = g_wq; bias = bq; Y = Yq; m0 = by << 7;         rnd = 1; }
    else if (by < 160) { X = g_mtok; W = g_wk; bias = bk; Y = Yk; m0 = (by - 128) << 7; rnd = 1; }
    else if (by < 192) { X = g_mtok; W = g_wv; bias = bv; Y = Yv; m0 = (by - 160) << 7; rnd = 0; }
    else               { X = g_ecls; W = g_wc; bias = bc; Y = Yc; m0 = 0;               rnd = 0; }

    const uint32_t stile = smem_u32(smem) + 1024;

    float c[4][8][4];
#pragma unroll
    for (int mt = 0; mt < 4; mt++)
#pragma unroll
        for (int nt = 0; nt < 8; nt++)
#pragma unroll
            for (int q = 0; q < 4; q++) c[mt][nt][q] = 0.0f;

    auto issue = [&](int kt, int s) {
        uint32_t ab = stile + s * P_STAGE_B;
        uint32_t bb = ab + A_TILE_B;
#pragma unroll
        for (int it = 0; it < 8; ++it) {
            int idx = tid + (it << 7);
            int r = idx >> 3, c4 = (idx & 7) << 2;
            cp16(ab + (uint32_t)(r * 36 + c4) * 4,
                 &X[(size_t)(m0 + r) * Dd + kt * 32 + c4]);
            int kk = idx >> 5, n4 = (idx & 31) << 2;
            cp16(bb + (uint32_t)(kk * 132 + n4) * 4,
                 &W[(size_t)(kt * 32 + kk) * Hh + n0 + n4]);
        }
    };

    issue(0, 0);
    CP_COMMIT();

    const int NKT = Dd / 32;  // 24
    for (int kt = 0; kt < NKT; ++kt) {
        if (kt + 1 < NKT) issue(kt + 1, (kt + 1) & 1);
        CP_COMMIT();
        CP_WAIT1();
        __syncthreads();

        const uint32_t* As = (const uint32_t*)(smem + 1024 + (kt & 1) * P_STAGE_B);
        const uint32_t* Bs = As + 128 * 36;

#pragma unroll
        for (int ks = 0; ks < 4; ++ks) {
            int k0 = ks << 3;
            uint32_t a[4][4];
#pragma unroll
            for (int mt = 0; mt < 4; mt++) {
                int r = wm * 64 + mt * 16 + gid;
                a[mt][0] = As[r * 36 + k0 + tg];
                a[mt][1] = As[(r + 8) * 36 + k0 + tg];
                a[mt][2] = As[r * 36 + k0 + tg + 4];
                a[mt][3] = As[(r + 8) * 36 + k0 + tg + 4];
            }
#pragma unroll
            for (int nt = 0; nt < 8; nt++) {
                int n = wn * 64 + nt * 8 + gid;
                uint32_t b0 = Bs[(k0 + tg) * 132 + n];
                uint32_t b1 = Bs[(k0 + tg + 4) * 132 + n];
#pragma unroll
                for (int mt = 0; mt < 4; mt++)
                    mma_tf32(c[mt][nt], a[mt], b0, b1);
            }
        }
        __syncthreads();
    }

    // epilogue: bias + (optional tf32 pre-round) + store
#pragma unroll
    for (int nt = 0; nt < 8; nt++) {
        int col = n0 + wn * 64 + nt * 8 + 2 * tg;
        float2 bvv = *(const float2*)&bias[col];
#pragma unroll
        for (int mt = 0; mt < 4; mt++) {
            int r = m0 + wm * 64 + mt * 16 + gid;
            float2 o0 = {c[mt][nt][0] + bvv.x, c[mt][nt][1] + bvv.y};
            float2 o1 = {c[mt][nt][2] + bvv.x, c[mt][nt][3] + bvv.y};
            if (rnd) {
                o0.x = __uint_as_float(f2tf(o0.x));
                o0.y = __uint_as_float(f2tf(o0.y));
                o1.x = __uint_as_float(f2tf(o1.x));
                o1.y = __uint_as_float(f2tf(o1.y));
            }
            *(float2*)&Y[(size_t)r * Hh + col] = o0;
            *(float2*)&Y[(size_t)(r + 8) * Hh + col] = o1;
        }
    }
}

// ---------------------------------------------------------------------------
// Fused attention: one CTA per (e,b), 128 threads (4 warps, 64x64 tiles).
//   Q/K pre-rounded tf32 -> cp.async raw bytes, 2-stage pipeline.
//   scores = Q_e @ K_b^T; per-thread-row softmax; pbar; ctx=pbar@V/S; LN; out
// smem: pbar[128]@0, red[4]@512, tiles@1024 (stage s: Q[128][36]+K[128][36]),
//       P[128][129] fp32 overlays tiles after mainloop
// ---------------------------------------------------------------------------
#define TILE_BYTES (128 * 36 * 4)          // 18432
#define STAGE_BYTES (2 * TILE_BYTES)       // 36864
#define OFF_TILE 1024
#define ATTN_SMEM (OFF_TILE + 2 * STAGE_BYTES)

__global__ __launch_bounds__(128, 2)
void attn_mma(const float* __restrict__ ecls, const float* __restrict__ mcls,
              const float* __restrict__ lng, const float* __restrict__ lnb,
              float* __restrict__ out)
{
    extern __shared__ char smem[];
    float* pbar = (float*)smem;                 // [128]
    float* red = (float*)(smem + 512);          // [4]
    float* P = (float*)(smem + OFF_TILE);       // [128][129] overlay

    const int tid = threadIdx.x;
    const int wid = tid >> 5;
    const int lane = tid & 31;
    const int gid = lane >> 2;
    const int tg = lane & 3;
    const int wm = wid & 1;
    const int wn = wid >> 1;
    const int e = blockIdx.x >> 5;
    const int b = blockIdx.x & 31;

    const float* __restrict__ Q = g_q + (size_t)e * Ss * Hh;
    const float* __restrict__ K = g_k + (size_t)b * Ss * Hh;
    const float* __restrict__ V = g_v + (size_t)b * Ss * Hh;

    const uint32_t stile = smem_u32(smem) + OFF_TILE;

    float c[4][8][4];
#pragma unroll
    for (int mt = 0; mt < 4; mt++)
#pragma unroll
        for (int nt = 0; nt < 8; nt++)
#pragma unroll
            for (int q = 0; q < 4; q++) c[mt][nt][q] = 0.0f;

    auto issue = [&](int kt, int s) {
        uint32_t qb = stile + s * STAGE_BYTES;
        uint32_t kb = qb + TILE_BYTES;
#pragma unroll
        for (int it = 0; it < 8; ++it) {
            int idx = tid + (it << 7);
            int r = idx >> 3, c4 = (idx & 7) << 2;
            uint32_t off = (uint32_t)(r * 36 + c4) * 4;
            cp16(qb + off, &Q[(size_t)r * Hh + kt * 32 + c4]);
            cp16(kb + off, &K[(size_t)r * Hh + kt * 32 + c4]);
        }
    };

    issue(0, 0);
    CP_COMMIT();

    const int NKT = Hh / 32;  // 24
    for (int kt = 0; kt < NKT; ++kt) {
        if (kt + 1 < NKT) issue(kt + 1, (kt + 1) & 1);
        CP_COMMIT();
        CP_WAIT1();
        __syncthreads();

        const uint32_t* Qs = (const uint32_t*)(smem + OFF_TILE + (kt & 1) * STAGE_BYTES);
        const uint32_t* Ks = Qs + 128 * 36;

#pragma unroll
        for (int ks = 0; ks < 4; ++ks) {
            int k0 = ks << 3;
            uint32_t a[4][4];
#pragma unroll
            for (int mt = 0; mt < 4; mt++) {
                int r = wm * 64 + mt * 16 + gid;
                a[mt][0] = Qs[r * 36 + k0 + tg];
                a[mt][1] = Qs[(r + 8) * 36 + k0 + tg];
                a[mt][2] = Qs[r * 36 + k0 + tg + 4];
                a[mt][3] = Qs[(r + 8) * 36 + k0 + tg + 4];
            }
#pragma unroll
            for (int nt = 0; nt < 8; nt++) {
                int n = wn * 64 + nt * 8 + gid;
                uint32_t b0 = Ks[n * 36 + k0 + tg];
                uint32_t b1 = Ks[n * 36 + k0 + tg + 4];
#pragma unroll
                for (int mt = 0; mt < 4; mt++)
                    mma_tf32(c[mt][nt], a[mt], b0, b1);
            }
        }
        __syncthreads();
    }

    // fragments -> P (raw scores)
#pragma unroll
    for (int nt = 0; nt < 8; nt++) {
        int col = wn * 64 + nt * 8 + 2 * tg;
#pragma unroll
        for (int mt = 0; mt < 4; mt++) {
            int r = wm * 64 + mt * 16 + gid;
            P[r * 129 + col] = c[mt][nt][0];
            P[r * 129 + col + 1] = c[mt][nt][1];
            P[(r + 8) * 129 + col] = c[mt][nt][2];
            P[(r + 8) * 129 + col + 1] = c[mt][nt][3];
        }
    }
    __syncthreads();

    // softmax: one thread per row, fully local
    const float scale = 0.0360843918243516f;  // 1/sqrt(768)
    {
        float* pr = &P[tid * 129];
        float m = -1e30f;
#pragma unroll 8
        for (int j = 0; j < 128; ++j) m = fmaxf(m, pr[j]);
        float s = 0.0f;
#pragma unroll 8
        for (int j = 0; j < 128; ++j) {
            float v = __expf((pr[j] - m) * scale);
            pr[j] = v;
            s += v;
        }
        float inv = 1.0f / s;
#pragma unroll 8
        for (int j = 0; j < 128; ++j) pr[j] *= inv;
    }
    __syncthreads();

    // pbar[t] = sum_s P[s][t]
    {
        float cs = 0.0f;
#pragma unroll 8
        for (int s = 0; s < 128; ++s) cs += P[s * 129 + tid];
        pbar[tid] = cs;
    }
    __syncthreads();

    // ctx[h] = (1/S) * sum_t pbar[t] * V[t,h]; each thread owns 6 h values
    float acc[6];
#pragma unroll
    for (int j = 0; j < 6; j++) acc[j] = 0.0f;
#pragma unroll 4
    for (int t = 0; t < Ss; t++) {
        float p = pbar[t];
        const float* vr = V + (size_t)t * Hh + tid;
#pragma unroll
        for (int j = 0; j < 6; j++) acc[j] += p * vr[128 * j];
    }
    const float invS = 1.0f / (float)Ss;
#pragma unroll
    for (int j = 0; j < 6; j++) acc[j] *= invS;

    // LayerNorm over 768
    float lsum = 0.0f, lsq = 0.0f;
#pragma unroll
    for (int j = 0; j < 6; j++) { lsum += acc[j]; lsq += acc[j] * acc[j]; }
    float tot = brsum(lsum, red, tid);
    float tot2 = brsum(lsq, red, tid);
    const float mu = tot * (1.0f / (float)Hh);
    const float var = tot2 * (1.0f / (float)Hh) - mu * mu;
    const float rstd = rsqrtf(var + LN_EPS);

    // g2l partial + g2g partial
    const float* __restrict__ cfc = g_c + (size_t)e * Hh;
    float p1 = 0.0f;
#pragma unroll
    for (int j = 0; j < 6; j++) {
        int h = tid + 128 * j;
        float x = (acc[j] - mu) * rstd * lng[h] + lnb[h];
        p1 += cfc[h] * x;
    }
    float p2 = 0.0f;
    {
        const float* mr = mcls + (size_t)b * Dd;
        const float* er = ecls + (size_t)e * Dd;
#pragma unroll
        for (int j = 0; j < 6; j++)
            p2 += mr[tid + 128 * j] * er[tid + 128 * j];
    }
    float g2l = brsum(p1, red, tid);
    float g2g = brsum(p2, red, tid);
    if (tid == 0) out[(size_t)b * Ee + e] = 0.5f * (g2l + g2g);
}

// ---------------------------------------------------------------------------
extern "C" void kernel_launch(void* const* d_in, const int* in_sizes, int n_in,
                              void* d_out, int out_size)
{
    const float* ecls = (const float*)d_in[0];
    const float* etok = (const float*)d_in[1];
    const float* mcls = (const float*)d_in[2];
    const float* mtok = (const float*)d_in[3];
    const float* Wq = (const float*)d_in[4];
    const float* bq = (const float*)d_in[5];
    const float* Wk = (const float*)d_in[6];
    const float* bk = (const float*)d_in[7];
    const float* Wv = (const float*)d_in[8];
    const float* bv = (const float*)d_in[9];
    const float* Wc = (const float*)d_in[10];
    const float* bc = (const float*)d_in[11];
    const float* lng = (const float*)d_in[12];
    const float* lnb = (const float*)d_in[13];
    float* out = (float*)d_out;

    float *q_ptr, *k_ptr, *v_ptr, *c_ptr;
    float *retok, *rmtok, *recls, *rwq, *rwk, *rwv, *rwc;
    cudaGetSymbolAddress((void**)&q_ptr, g_q);
    cudaGetSymbolAddress((void**)&k_ptr, g_k);
    cudaGetSymbolAddress((void**)&v_ptr, g_v);
    cudaGetSymbolAddress((void**)&c_ptr, g_c);
    cudaGetSymbolAddress((void**)&retok, g_etok);
    cudaGetSymbolAddress((void**)&rmtok, g_mtok);
    cudaGetSymbolAddress((void**)&recls, g_ecls);
    cudaGetSymbolAddress((void**)&rwq, g_wq);
    cudaGetSymbolAddress((void**)&rwk, g_wk);
    cudaGetSymbolAddress((void**)&rwv, g_wv);
    cudaGetSymbolAddress((void**)&rwc, g_wc);

    cudaFuncSetAttribute(proj_mma, cudaFuncAttributeMaxDynamicSharedMemorySize, PROJ_SMEM);
    cudaFuncSetAttribute(attn_mma, cudaFuncAttributeMaxDynamicSharedMemorySize, ATTN_SMEM);

    // pre-round inputs to tf32 (rna) copies
    auto launch_round = [&](const float* s, float* d, int n) {
        int n4 = n >> 2;
        round_pre<<<(n4 + 255) / 256, 256>>>(s, d, n4);
    };
    launch_round(etok, retok, Ee * Ss * Dd);
    launch_round(mtok, rmtok, Bb * Ss * Dd);
    launch_round(ecls, recls, Ee * Dd);
    launch_round(Wq, rwq, Dd * Hh);
    launch_round(Wk, rwk, Dd * Hh);
    launch_round(Wv, rwv, Dd * Hh);
    launch_round(Wc, rwc, Dd * Hh);

    proj_mma<<<dim3(Hh / 128, 193), 128, PROJ_SMEM>>>(
        bq, bk, bv, bc, q_ptr, k_ptr, v_ptr, c_ptr);

    attn_mma<<<dim3(Ee * Bb), 128, ATTN_SMEM>>>(ecls, mcls, lng, lnb, out);
}